// round 2
// baseline (speedup 1.0000x reference)
#include <cuda_runtime.h>
#include <cstdint>

// Shape fixed by dataset: (64, 68, 128, 128) fp32 x2.
static constexpr int NIMG      = 64 * 68;          // 4352 images
static constexpr int IMG_ELEMS = 128 * 128;
static constexpr int TASKS     = NIMG * 2;         // half-image per warp
static constexpr int WARPS     = 8;                // warps per block
static constexpr int NBLK      = TASKS / WARPS;    // 1088 blocks
static constexpr double TOTAL_ELEMS = 71303168.0;

__device__ double       g_part[NBLK];
__device__ unsigned int g_count = 0;               // self-resetting each launch

__device__ __forceinline__ float ex2a(float x) {
    float y; asm("ex2.approx.f32 %0, %1;" : "=f"(y) : "f"(x)); return y;
}
__device__ __forceinline__ float lg2a(float x) {
    float y; asm("lg2.approx.f32 %0, %1;" : "=f"(y) : "f"(x)); return y;
}

// Horizontal 3-max (SAME padding) of a row held as float4-per-lane.
// Edge lanes use the clipped window directly (no NEG_INF needed).
__device__ __forceinline__ float4 hmax3(float4 v, bool lane0, bool lane31) {
    float left  = __shfl_up_sync(0xffffffffu, v.w, 1);
    float right = __shfl_down_sync(0xffffffffu, v.x, 1);
    float m01 = fmaxf(v.x, v.y);
    float m12 = fmaxf(v.y, v.z);
    float m23 = fmaxf(v.z, v.w);
    float4 h;
    h.x = lane0  ? m01 : fmaxf(left, m01);
    h.y = fmaxf(v.x, m12);
    h.z = fmaxf(v.y, m23);
    h.w = lane31 ? m23 : fmaxf(m23, right);
    return h;
}

// loss = 14*ln(1+s) + 28*asl*s/(1+s) * max(d-0.5, 0),  s = min(d,0.5)^asl
// Exact rewrite of the reference: when relu>0, s == T1 == 0.5^asl exactly.
// 1/(1+s) on the relu-active range s in (0.233, 0.467): 3-term series around 0.35.
__device__ __forceinline__ void elem(float p, float l, float vm,
                                     float& acc, float& accm) {
    float d    = fabsf(p - l);
    float m    = fminf(d, 0.5f);
    float asl  = 2.1f - l;
    float s    = ex2a(asl * lg2a(m));
    float lossA = 9.70406052783923f * lg2a(1.0f + s);       // 14*ln(1+s)
    float z    = fmaf(s, 0.7407407407407407f, -0.25925925925925924f);
    float i1   = 1.0f - z;
    float i2   = fmaf(-z, i1, 1.0f);
    float i3   = fmaf(-z, i2, 1.0f);                        // ~1.35/(1+s)
    float q    = (asl * s) * i3;
    float relu = (d - m) * 20.74074074074074f;              // 28/1.35 folded
    float loss = fmaf(q, relu, lossA);
    acc += loss;
    if (vm >= 0.1f) accm += loss;                           // == 255*max3x3 >= 25.5
}

__global__ void __launch_bounds__(256)
awing(const float* __restrict__ pred, const float* __restrict__ lmk,
      float* __restrict__ out) {
    const int  lane = threadIdx.x & 31;
    const int  wid  = threadIdx.x >> 5;
    const int  task = blockIdx.x * WARPS + wid;
    const int  img  = task >> 1;
    const int  half = task & 1;
    const bool la0  = (lane == 0), la31 = (lane == 31);

    const size_t base = (size_t)img * IMG_ELEMS + (size_t)half * 64 * 128;
    const float4* lp = reinterpret_cast<const float4*>(lmk  + base) + lane;
    const float4* pp = reinterpret_cast<const float4*>(pred + base) + lane;

    // half==0: no clamp really needed (rows beyond exist); half==1: clamp at
    // local row 63 -> duplicates global row 127 == SAME padding for the max.
    const int clampIdx = half ? 63 : 127;
    const int prevOff  = half ? -32 : 0;   // row -1; half==0 duplicates row 0 (SAME)

    float4 l_m1  = lp[prevOff];
    float4 l_cur = lp[0];
    float4 l_nxt = lp[32];
    float4 p_cur = pp[0];

    float4 hprev = hmax3(l_m1,  la0, la31);
    float4 hcur  = hmax3(l_cur, la0, la31);

    float acc = 0.0f, accm = 0.0f;

#pragma unroll 2
    for (int r = 0; r < 64; ++r) {
        int li = min(r + 2, clampIdx);
        int pi = min(r + 1, clampIdx);
        float4 l_pf = lp[li * 32];
        float4 p_pf = pp[pi * 32];

        float4 hnext = hmax3(l_nxt, la0, la31);

        float vx = fmaxf(hprev.x, fmaxf(hcur.x, hnext.x));
        float vy = fmaxf(hprev.y, fmaxf(hcur.y, hnext.y));
        float vz = fmaxf(hprev.z, fmaxf(hcur.z, hnext.z));
        float vw = fmaxf(hprev.w, fmaxf(hcur.w, hnext.w));

        elem(p_cur.x, l_cur.x, vx, acc, accm);
        elem(p_cur.y, l_cur.y, vy, acc, accm);
        elem(p_cur.z, l_cur.z, vz, acc, accm);
        elem(p_cur.w, l_cur.w, vw, acc, accm);

        hprev = hcur; hcur = hnext;
        l_cur = l_nxt; l_nxt = l_pf;
        p_cur = p_pf;
    }

    // Deterministic reduction: fixed xor tree within warp.
    float tot = fmaf(accm, 10.0f, acc);
#pragma unroll
    for (int o = 16; o; o >>= 1)
        tot += __shfl_xor_sync(0xffffffffu, tot, o);

    __shared__ float  wsum[WARPS];
    __shared__ double sh[256];
    __shared__ bool   isLast;
    if (lane == 0) wsum[wid] = tot;
    __syncthreads();
    if (threadIdx.x == 0) {
        double s = 0.0;
#pragma unroll
        for (int i = 0; i < WARPS; ++i) s += (double)wsum[i];
        g_part[blockIdx.x] = s;
        __threadfence();
        unsigned int old = atomicAdd(&g_count, 1u);
        isLast = (old == (unsigned)(NBLK - 1));
        if (isLast) g_count = 0;                 // reset for next graph replay
    }
    __syncthreads();

    if (isLast) {
        double s = 0.0;
        for (int i = threadIdx.x; i < NBLK; i += 256)
            s += __ldcg(&g_part[i]);
        sh[threadIdx.x] = s;
        __syncthreads();
#pragma unroll
        for (int k = 128; k; k >>= 1) {
            if (threadIdx.x < k) sh[threadIdx.x] += sh[threadIdx.x + k];
            __syncthreads();
        }
        if (threadIdx.x == 0)
            out[0] = (float)(sh[0] * (1.0 / TOTAL_ELEMS));
    }
}

extern "C" void kernel_launch(void* const* d_in, const int* in_sizes, int n_in,
                              void* d_out, int out_size) {
    const float* pred = (const float*)d_in[0];
    const float* lmk  = (const float*)d_in[1];
    awing<<<NBLK, 256>>>(pred, lmk, (float*)d_out);
}

// round 3
// speedup vs baseline: 1.4107x; 1.4107x over previous
#include <cuda_runtime.h>
#include <cstdint>

// Shape fixed by dataset: (64, 68, 128, 128) fp32 x2.
static constexpr int NIMG      = 64 * 68;        // 4352 images, 1 per warp
static constexpr int IMG_ELEMS = 128 * 128;
static constexpr int WARPS     = 8;
static constexpr int NBLK      = NIMG / WARPS;   // 544 blocks -> single wave
static constexpr double TOTAL_ELEMS = 71303168.0;

__device__ double       g_part[NBLK];
__device__ unsigned int g_count = 0;             // self-resetting each launch

__device__ __forceinline__ float ex2a(float x) {
    float y; asm("ex2.approx.f32 %0, %1;" : "=f"(y) : "f"(x)); return y;
}
__device__ __forceinline__ float lg2a(float x) {
    float y; asm("lg2.approx.f32 %0, %1;" : "=f"(y) : "f"(x)); return y;
}

// Horizontal 3-max with SAME padding (edge lanes use clipped window).
__device__ __forceinline__ float4 hmax3(float4 v, bool la0, bool la31) {
    float left  = __shfl_up_sync(0xffffffffu, v.w, 1);
    float right = __shfl_down_sync(0xffffffffu, v.x, 1);
    float m01 = fmaxf(v.x, v.y);
    float m12 = fmaxf(v.y, v.z);
    float m23 = fmaxf(v.z, v.w);
    float4 h;
    h.x = la0  ? m01 : fmaxf(left, m01);
    h.y = fmaxf(v.x, m12);
    h.z = fmaxf(v.y, m23);
    h.w = la31 ? m23 : fmaxf(m23, right);
    return h;
}

// loss = 14*ln(1+s) + [28*asl*s/(1+s)] * max(d-0.5,0),  s = min(d,0.5)^asl.
// Exact rewrite of reference (when relu>0, s == T1 == 0.5^asl exactly).
// K/(1+s) on relu-active range s in (0.233,0.467) via Horner 3-FMA series
// around s=0.35 (z = (1+s)/1.35 - 1, rel err <= 5.6e-5).
__device__ __forceinline__ void elem(float p, float l, float vm,
                                     float& acc, float& accm) {
    const float K = 20.74074074074074f;                    // 28/1.35
    float d0   = p - l;                                    // |d0| via modifiers
    float m    = fminf(fabsf(d0), 0.5f);
    float asl  = 2.1f - l;
    float s    = ex2a(asl * lg2a(m));
    float lossA = 9.70406052783923f * lg2a(1.0f + s);      // 14*ln(1+s)
    float z    = fmaf(s, 0.7407407407407407f, -0.25925925925925924f);
    float t1   = fmaf(z, -K, K);
    float t2   = fmaf(-z, t1, K);
    float t3   = fmaf(-z, t2, K);                          // ~28/(1+s)
    float q    = (asl * s) * t3;
    float relu = fabsf(d0) - m;                            // max(d-0.5, 0)
    float loss = fmaf(q, relu, lossA);
    acc += loss;
    if (vm >= 0.1f) accm += loss;                          // 255*max3x3 >= 25.5
}

__global__ void __launch_bounds__(256, 4)
awing(const float* __restrict__ pred, const float* __restrict__ lmk,
      float* __restrict__ out) {
    const int  lane = threadIdx.x & 31;
    const int  wid  = threadIdx.x >> 5;
    const int  img  = blockIdx.x * WARPS + wid;
    const bool la0  = (lane == 0), la31 = (lane == 31);

    const float4* lp = reinterpret_cast<const float4*>(lmk  + (size_t)img * IMG_ELEMS) + lane;
    const float4* pp = reinterpret_cast<const float4*>(pred + (size_t)img * IMG_ELEMS) + lane;

    // Software-pipelined state at top of iter r:
    //   hprev=h(r-1), hcur=h(r), l_cur=l[r], lA=l[r+1], lB=l[r+2],
    //   p_cur=p[r], p_nxt=p[r+1]; this iter loads l[r+3], p[r+2].
    float4 l_cur = lp[0];
    float4 lA    = lp[32];
    float4 lB    = lp[64];
    float4 p_cur = pp[0];
    float4 p_nxt = pp[32];

    float4 hcur  = hmax3(l_cur, la0, la31);
    float4 hprev = hcur;                 // SAME padding: h(-1) := h(0)

    float acc = 0.0f, accm = 0.0f;

#pragma unroll 4
    for (int r = 0; r < 128; ++r) {
        // Clamped row duplication == SAME padding for the max window.
        int li = min(r + 3, 127);
        int pi = min(r + 2, 127);
        float4 lC = lp[li * 32];
        float4 pC = pp[pi * 32];

        float4 hnext = hmax3(lA, la0, la31);

        float vx = fmaxf(hprev.x, fmaxf(hcur.x, hnext.x));
        float vy = fmaxf(hprev.y, fmaxf(hcur.y, hnext.y));
        float vz = fmaxf(hprev.z, fmaxf(hcur.z, hnext.z));
        float vw = fmaxf(hprev.w, fmaxf(hcur.w, hnext.w));

        elem(p_cur.x, l_cur.x, vx, acc, accm);
        elem(p_cur.y, l_cur.y, vy, acc, accm);
        elem(p_cur.z, l_cur.z, vz, acc, accm);
        elem(p_cur.w, l_cur.w, vw, acc, accm);

        hprev = hcur; hcur = hnext;
        l_cur = lA; lA = lB; lB = lC;
        p_cur = p_nxt; p_nxt = pC;
    }

    float tot = fmaf(accm, 10.0f, acc);
#pragma unroll
    for (int o = 16; o; o >>= 1)
        tot += __shfl_xor_sync(0xffffffffu, tot, o);

    __shared__ float  wsum[WARPS];
    __shared__ double sh[256];
    __shared__ bool   isLast;
    if (lane == 0) wsum[wid] = tot;
    __syncthreads();
    if (threadIdx.x == 0) {
        double s = 0.0;
#pragma unroll
        for (int i = 0; i < WARPS; ++i) s += (double)wsum[i];
        g_part[blockIdx.x] = s;
        __threadfence();
        unsigned int old = atomicAdd(&g_count, 1u);
        isLast = (old == (unsigned)(NBLK - 1));
        if (isLast) g_count = 0;             // reset for next graph replay
    }
    __syncthreads();

    if (isLast) {
        double s = 0.0;
        for (int i = threadIdx.x; i < NBLK; i += 256)
            s += __ldcg(&g_part[i]);
        sh[threadIdx.x] = s;
        __syncthreads();
#pragma unroll
        for (int k = 128; k; k >>= 1) {
            if (threadIdx.x < k) sh[threadIdx.x] += sh[threadIdx.x + k];
            __syncthreads();
        }
        if (threadIdx.x == 0)
            out[0] = (float)(sh[0] * (1.0 / TOTAL_ELEMS));
    }
}

extern "C" void kernel_launch(void* const* d_in, const int* in_sizes, int n_in,
                              void* d_out, int out_size) {
    const float* pred = (const float*)d_in[0];
    const float* lmk  = (const float*)d_in[1];
    awing<<<NBLK, 256>>>(pred, lmk, (float*)d_out);
}